// round 14
// baseline (speedup 1.0000x reference)
#include <cuda_runtime.h>
#include <math.h>
#include <stdint.h>

#define R 32
#define V 50257
#define VR (V * R)              // floats per i-slab (contiguous)
#define L4 (VR / 4)             // 402,056 float4 per slab
#define BATCH 1024
#define NSTEP 8
#define EPS 1e-10f

#define THREADS 256
#define GATHER_BLOCKS 128       // 1024 warps = 1 / batch row
#define STREAM_BLOCKS 608
#define NBLOCKS (GATHER_BLOCKS + STREAM_BLOCKS)  // 736 <= 5/SM * 152

#define DEPTH 5                 // TMA ring stages (proven config)
#define STAGE_F4 512            // 8 KB per full stage
#define UNITS_PER_SLAB 786      // 785 full + 1 tail(136 f4)
#define NUNITS (UNITS_PER_SLAB * R)   // 25,152
#define TAIL_F4 136             // 402,056 - 785*512

// Scratch (no allocation anywhere). All zero at module load; finalize
// self-resets them each call -> graph-replay safe with no memset node.
__device__ float g_M[R * R];
__device__ float g_pt[BATCH];
__device__ unsigned int g_work = 0;    // stream work-queue ticket
__device__ unsigned int g_count = 0;   // completion counter

// ---- PTX helpers -----------------------------------------------------------
__device__ __forceinline__ void mbar_init(uint32_t a, uint32_t cnt) {
    asm volatile("mbarrier.init.shared.b64 [%0], %1;" :: "r"(a), "r"(cnt) : "memory");
}
__device__ __forceinline__ void mbar_expect_tx(uint32_t a, uint32_t bytes) {
    asm volatile("mbarrier.arrive.expect_tx.shared.b64 _, [%0], %1;"
                 :: "r"(a), "r"(bytes) : "memory");
}
__device__ __forceinline__ void mbar_wait(uint32_t a, uint32_t parity) {
    uint32_t done;
    asm volatile("{\n\t.reg .pred p;\n\t"
                 "mbarrier.try_wait.parity.acquire.cta.shared::cta.b64 p, [%1], %2;\n\t"
                 "selp.b32 %0, 1, 0, p;\n\t}"
                 : "=r"(done) : "r"(a), "r"(parity) : "memory");
    if (!done) {
        asm volatile("{\n\t.reg .pred P1;\n\t"
                     "W_%=:\n\t"
                     "mbarrier.try_wait.parity.acquire.cta.shared::cta.b64 P1, [%0], %1, 0x989680;\n\t"
                     "@P1 bra.uni D_%=;\n\t"
                     "bra.uni W_%=;\n\t"
                     "D_%=:\n\t}" :: "r"(a), "r"(parity) : "memory");
    }
}
__device__ __forceinline__ void bulk_g2s(uint32_t smem_dst, const void* gsrc,
                                         uint32_t bytes, uint32_t mbar) {
    asm volatile("cp.async.bulk.shared::cluster.global.mbarrier::complete_tx::bytes "
                 "[%0], [%1], %2, [%3];"
                 :: "r"(smem_dst), "l"(gsrc), "r"(bytes), "r"(mbar) : "memory");
}

__global__ __launch_bounds__(THREADS)
void tjd_fused_kernel(const float* __restrict__ alpha,
                      const float* __restrict__ beta,
                      const float* __restrict__ core,
                      const int*   __restrict__ ids,
                      float* __restrict__ out, int out_size)
{
    const int bid = blockIdx.x;
    const int tid = threadIdx.x;

    __shared__ __align__(16) union SmemU {
        float4 buf[DEPTH][STAGE_F4];                      // 40 KB ring
        struct { float sM[R * R]; float sloss[THREADS]; } fin;
    } u;
    __shared__ __align__(8) unsigned long long mbar[DEPTH];
    __shared__ int   s_unit[DEPTH];   // unit id per slot (-1 = none)
    __shared__ float sred[R];
    __shared__ float s_z;
    __shared__ int   s_last;

    if (bid < GATHER_BLOCKS) {
        // ---------------- gather/chain: one warp per batch row ----------------
        const int row  = bid * (THREADS / 32) + (tid >> 5);
        const int lane = tid & 31;
        const int* myids = ids + row * NSTEP;

        float v = fmaxf(alpha[lane], 0.0f) + EPS;

        #pragma unroll 1
        for (int t = 0; t < NSTEP; t++) {
            const float* base = core + (size_t)myids[t] * R + lane;
            float g[R];
            #pragma unroll
            for (int k = 0; k < R; k++)
                g[k] = __ldg(base + (size_t)k * VR);
            float nv = 0.0f;
            #pragma unroll
            for (int k = 0; k < R; k++)
                nv = fmaf(__shfl_sync(0xffffffffu, v, k),
                          fmaxf(g[k], 0.0f) + EPS, nv);
            v = nv;
        }

        float pt = v * (fmaxf(beta[lane], 0.0f) + EPS);
        #pragma unroll
        for (int o = 16; o; o >>= 1)
            pt += __shfl_xor_sync(0xffffffffu, pt, o);
        if (lane == 0) g_pt[row] = pt;
    } else {
        // ------ work-queue streaming reduction via TMA bulk copies -----------
        const float4* core4 = (const float4*)core;
        const uint32_t buf0  = (uint32_t)__cvta_generic_to_shared(&u.buf[0][0]);
        const uint32_t mbar0 = (uint32_t)__cvta_generic_to_shared(&mbar[0]);

        if (tid == 0) {
            #pragma unroll
            for (int s = 0; s < DEPTH; s++) mbar_init(mbar0 + 8u * s, 1u);
        }
        __syncthreads();

        // prologue: grab DEPTH units, issue their copies
        if (tid == 0) {
            #pragma unroll
            for (int s = 0; s < DEPTH; s++) {
                unsigned w = atomicAdd(&g_work, 1u);
                if (w < NUNITS) {
                    const int slab = w / UNITS_PER_SLAB;
                    const int k    = w % UNITS_PER_SLAB;
                    const int cnt  = (k == UNITS_PER_SLAB - 1) ? TAIL_F4 : STAGE_F4;
                    s_unit[s] = (int)w;
                    mbar_expect_tx(mbar0 + 8u * s, (uint32_t)cnt * 16u);
                    bulk_g2s(buf0 + (uint32_t)s * (STAGE_F4 * 16),
                             core4 + (size_t)slab * L4 + (size_t)k * STAGE_F4,
                             (uint32_t)cnt * 16u, mbar0 + 8u * s);
                } else {
                    s_unit[s] = -1;
                }
            }
        }
        __syncthreads();

        const int jb = (tid & 7) * 4;     // unit starts are mult of 8 f4
        float x0=0.f, y0=0.f, z0=0.f, w0=0.f;
        float x1=0.f, y1=0.f, z1=0.f, w1=0.f;
        int accSlab = -1;

        #pragma unroll 1
        for (int st = 0; ; st++) {
            const int slot = st % DEPTH;
            const int unit = s_unit[slot];
            if (unit < 0) break;
            const int slab = unit / UNITS_PER_SLAB;
            const int k    = unit % UNITS_PER_SLAB;
            const int cnt  = (k == UNITS_PER_SLAB - 1) ? TAIL_F4 : STAGE_F4;

            // flush accumulator on slab change (uniform decision, all threads)
            if (slab != accSlab) {
                if (accSlab >= 0) {
                    if (tid < R) sred[tid] = 0.0f;
                    __syncthreads();
                    atomicAdd(&sred[jb + 0], x0 + x1);
                    atomicAdd(&sred[jb + 1], y0 + y1);
                    atomicAdd(&sred[jb + 2], z0 + z1);
                    atomicAdd(&sred[jb + 3], w0 + w1);
                    __syncthreads();
                    if (tid < R) atomicAdd(&g_M[accSlab * R + tid], sred[tid]);
                    x0=y0=z0=w0=0.f; x1=y1=z1=w1=0.f;
                    __syncthreads();      // sred reusable next flush
                }
                accSlab = slab;
            }

            mbar_wait(mbar0 + 8u * slot, (uint32_t)((st / DEPTH) & 1));

            if (cnt == STAGE_F4) {
                float4 g0 = u.buf[slot][tid];
                float4 g1 = u.buf[slot][tid + 256];
                x0 += fmaxf(g0.x,0.f); y0 += fmaxf(g0.y,0.f);
                z0 += fmaxf(g0.z,0.f); w0 += fmaxf(g0.w,0.f);
                x1 += fmaxf(g1.x,0.f); y1 += fmaxf(g1.y,0.f);
                z1 += fmaxf(g1.z,0.f); w1 += fmaxf(g1.w,0.f);
            } else if (tid < cnt) {
                float4 g0 = u.buf[slot][tid];
                x0 += fmaxf(g0.x,0.f); y0 += fmaxf(g0.y,0.f);
                z0 += fmaxf(g0.z,0.f); w0 += fmaxf(g0.w,0.f);
            }

            __syncthreads();                      // slot fully consumed
            if (tid == 0) {
                unsigned w = atomicAdd(&g_work, 1u);
                if (w < NUNITS) {
                    const int nslab = w / UNITS_PER_SLAB;
                    const int nk    = w % UNITS_PER_SLAB;
                    const int ncnt  = (nk == UNITS_PER_SLAB - 1) ? TAIL_F4 : STAGE_F4;
                    s_unit[slot] = (int)w;
                    mbar_expect_tx(mbar0 + 8u * slot, (uint32_t)ncnt * 16u);
                    bulk_g2s(buf0 + (uint32_t)slot * (STAGE_F4 * 16),
                             core4 + (size_t)nslab * L4 + (size_t)nk * STAGE_F4,
                             (uint32_t)ncnt * 16u, mbar0 + 8u * slot);
                } else {
                    s_unit[slot] = -1;
                }
            }
            __syncthreads();                      // publish s_unit[slot]
        }

        // final flush
        if (accSlab >= 0) {
            if (tid < R) sred[tid] = 0.0f;
            __syncthreads();
            atomicAdd(&sred[jb + 0], x0 + x1);
            atomicAdd(&sred[jb + 1], y0 + y1);
            atomicAdd(&sred[jb + 2], z0 + z1);
            atomicAdd(&sred[jb + 3], w0 + w1);
            __syncthreads();
            if (tid < R) atomicAdd(&g_M[accSlab * R + tid], sred[tid]);
        }
    }

    // ------------------- last-block-done finalize -------------------
    __syncthreads();
    if (tid == 0) {
        __threadfence();
        s_last = (atomicAdd(&g_count, 1u) == (unsigned)(NBLOCKS - 1));
    }
    __syncthreads();
    if (!s_last) return;

    // consume g_M and reset scratch for the next graph replay
    for (int e = tid; e < R * R; e += THREADS) {
        u.fin.sM[e] = g_M[e] + (float)V * EPS;
        g_M[e] = 0.0f;
    }
    __syncthreads();

    if (tid < R) {
        float uu = fmaxf(alpha[tid], 0.0f) + EPS;
        #pragma unroll 1
        for (int s = 0; s < NSTEP; s++) {
            float nu = 0.0f;
            #pragma unroll
            for (int k = 0; k < R; k++)
                nu = fmaf(__shfl_sync(0xffffffffu, uu, k),
                          u.fin.sM[k * R + tid], nu);
            uu = nu;                 // overflows to +inf like fp32 reference
        }
        float z = uu * (fmaxf(beta[tid], 0.0f) + EPS);
        #pragma unroll
        for (int o = 16; o; o >>= 1)
            z += __shfl_xor_sync(0xffffffffu, z, o);
        if (tid == 0) s_z = z;
    }
    __syncthreads();

    const float z = s_z;
    float lacc = 0.0f;
    for (int row = tid; row < BATCH; row += THREADS) {
        const float prob = g_pt[row] / z;
        if (out_size >= BATCH + 1)  out[1 + row] = prob;
        else if (out_size == BATCH) out[row]     = prob;
        lacc -= logf(prob + EPS);
    }
    u.fin.sloss[tid] = lacc;
    __syncthreads();
    #pragma unroll
    for (int s = THREADS / 2; s > 0; s >>= 1) {
        if (tid < s) u.fin.sloss[tid] += u.fin.sloss[tid + s];
        __syncthreads();
    }
    if (tid == 0) {
        if (out_size != BATCH) out[0] = u.fin.sloss[0] / (float)BATCH;
        g_work  = 0;
        g_count = 0;
    }
}

// ---------------------------------------------------------------------------
extern "C" void kernel_launch(void* const* d_in, const int* in_sizes, int n_in,
                              void* d_out, int out_size) {
    const float* alpha = (const float*)d_in[0];   // (32,)
    const float* beta  = (const float*)d_in[1];   // (32,)
    const float* core  = (const float*)d_in[2];   // (32, 50257, 32)
    const int*   ids   = (const int*)  d_in[3];   // (1024, 8)

    tjd_fused_kernel<<<NBLOCKS, THREADS>>>(alpha, beta, core, ids,
                                           (float*)d_out, out_size);
}

// round 15
// speedup vs baseline: 2.7984x; 2.7984x over previous
#include <cuda_runtime.h>
#include <math.h>
#include <stdint.h>

#define R 32
#define V 50257
#define VR (V * R)              // floats per i-slab (contiguous)
#define L4 (VR / 4)             // 402,056 float4 per slab
#define BATCH 1024
#define NSTEP 8
#define EPS 1e-10f

#define THREADS 256
#define GATHER_BLOCKS 128       // 1024 warps = 1 / batch row
#define RED_BX 19               // reduction chunks per slab
#define RED_BLOCKS (RED_BX * R)               // 608
#define NBLOCKS (GATHER_BLOCKS + RED_BLOCKS)  // 736 (one wave @ 5/SM)
#define CHUNK_F4 21168          // per-chunk float4 (mod 8 == 0), last clipped

#define DEPTH 5                 // bulk-copy ring stages (best-measured config)
#define STAGE_F4 512            // 8 KB per stage, 2 float4 per thread
#define STAGE_BYTES (STAGE_F4 * 16)

// Scratch (no allocation anywhere). All zero at module load; finalize
// self-resets each call -> graph-replay safe with no memset node.
__device__ float g_M[R * R];
__device__ float g_pt[BATCH];
__device__ unsigned int g_count = 0;

// ---- PTX helpers -----------------------------------------------------------
__device__ __forceinline__ void mbar_init(uint32_t a, uint32_t cnt) {
    asm volatile("mbarrier.init.shared.b64 [%0], %1;" :: "r"(a), "r"(cnt) : "memory");
}
__device__ __forceinline__ void mbar_expect_tx(uint32_t a, uint32_t bytes) {
    asm volatile("mbarrier.arrive.expect_tx.shared.b64 _, [%0], %1;"
                 :: "r"(a), "r"(bytes) : "memory");
}
__device__ __forceinline__ void mbar_wait(uint32_t a, uint32_t parity) {
    uint32_t done;
    asm volatile("{\n\t.reg .pred p;\n\t"
                 "mbarrier.try_wait.parity.acquire.cta.shared::cta.b64 p, [%1], %2;\n\t"
                 "selp.b32 %0, 1, 0, p;\n\t}"
                 : "=r"(done) : "r"(a), "r"(parity) : "memory");
    if (!done) {
        asm volatile("{\n\t.reg .pred P1;\n\t"
                     "W_%=:\n\t"
                     "mbarrier.try_wait.parity.acquire.cta.shared::cta.b64 P1, [%0], %1, 0x989680;\n\t"
                     "@P1 bra.uni D_%=;\n\t"
                     "bra.uni W_%=;\n\t"
                     "D_%=:\n\t}" :: "r"(a), "r"(parity) : "memory");
    }
}
__device__ __forceinline__ void bulk_g2s(uint32_t smem_dst, const void* gsrc,
                                         uint32_t bytes, uint32_t mbar) {
    asm volatile("cp.async.bulk.shared::cluster.global.mbarrier::complete_tx::bytes "
                 "[%0], [%1], %2, [%3];"
                 :: "r"(smem_dst), "l"(gsrc), "r"(bytes), "r"(mbar) : "memory");
}

__global__ __launch_bounds__(THREADS)
void tjd_fused_kernel(const float* __restrict__ alpha,
                      const float* __restrict__ beta,
                      const float* __restrict__ core,
                      const int*   __restrict__ ids,
                      float* __restrict__ out, int out_size)
{
    const int bid = blockIdx.x;
    const int tid = threadIdx.x;

    // 40 KB bulk ring unioned with finalize scratch (used only after drain).
    __shared__ __align__(16) union SmemU {
        float4 buf[DEPTH][STAGE_F4];                      // 40 KB
        struct { float sM[R * R]; float sloss[THREADS]; } fin;
    } u;
    __shared__ __align__(8) unsigned long long mbar[DEPTH];
    __shared__ float sred[R];
    __shared__ float s_z;
    __shared__ int   s_last;

    if (bid < GATHER_BLOCKS) {
        // ---------------- gather/chain: one warp per batch row ----------------
        const int row  = bid * (THREADS / 32) + (tid >> 5);
        const int lane = tid & 31;
        const int* myids = ids + row * NSTEP;

        float v = fmaxf(alpha[lane], 0.0f) + EPS;

        #pragma unroll 1
        for (int t = 0; t < NSTEP; t++) {
            const float* base = core + (size_t)myids[t] * R + lane;
            float g[R];
            #pragma unroll
            for (int k = 0; k < R; k++)
                g[k] = __ldg(base + (size_t)k * VR);
            float nv = 0.0f;
            #pragma unroll
            for (int k = 0; k < R; k++)
                nv = fmaf(__shfl_sync(0xffffffffu, v, k),
                          fmaxf(g[k], 0.0f) + EPS, nv);
            v = nv;
        }

        float pt = v * (fmaxf(beta[lane], 0.0f) + EPS);
        #pragma unroll
        for (int o = 16; o; o >>= 1)
            pt += __shfl_xor_sync(0xffffffffu, pt, o);
        if (lane == 0) g_pt[row] = pt;
    } else {
        // ------ reduction via TMA-path bulk copies: M[i][j] = sum_v relu ------
        const int rb = bid - GATHER_BLOCKS;
        const int i  = rb / RED_BX;
        const int bx = rb % RED_BX;

        const float4* slab = (const float4*)(core + (size_t)i * VR);
        const int start = bx * CHUNK_F4;
        const int end   = (start + CHUNK_F4 < L4) ? start + CHUNK_F4 : L4;
        const int nfull = (end - start) / STAGE_F4;
        const float4* reg0 = slab + start;

        const uint32_t buf0  = (uint32_t)__cvta_generic_to_shared(&u.buf[0][0]);
        const uint32_t mbar0 = (uint32_t)__cvta_generic_to_shared(&mbar[0]);

        if (tid == 0) {
            #pragma unroll
            for (int s = 0; s < DEPTH; s++) mbar_init(mbar0 + 8u * s, 1u);
        }
        __syncthreads();

        if (tid == 0) {
            const int pre = (nfull < DEPTH) ? nfull : DEPTH;
            for (int s = 0; s < pre; s++) {
                mbar_expect_tx(mbar0 + 8u * s, STAGE_BYTES);
                bulk_g2s(buf0 + (uint32_t)s * STAGE_BYTES,
                         reg0 + (size_t)s * STAGE_F4, STAGE_BYTES,
                         mbar0 + 8u * s);
            }
        }

        float x0=0.f, y0=0.f, z0=0.f, w0=0.f;
        float x1=0.f, y1=0.f, z1=0.f, w1=0.f;

        #pragma unroll 1
        for (int st = 0; st < nfull; st++) {
            const int slot = st % DEPTH;
            mbar_wait(mbar0 + 8u * slot, (uint32_t)((st / DEPTH) & 1));

            // 2 float4 per thread, stride 256 (mod 8 == 0 -> fixed j-lanes)
            float4 g0 = u.buf[slot][tid];
            float4 g1 = u.buf[slot][tid + 256];
            x0 += fmaxf(g0.x,0.f); y0 += fmaxf(g0.y,0.f);
            z0 += fmaxf(g0.z,0.f); w0 += fmaxf(g0.w,0.f);
            x1 += fmaxf(g1.x,0.f); y1 += fmaxf(g1.y,0.f);
            z1 += fmaxf(g1.z,0.f); w1 += fmaxf(g1.w,0.f);

            __syncthreads();                      // slot fully consumed
            if (tid == 0 && st + DEPTH < nfull) {
                mbar_expect_tx(mbar0 + 8u * slot, STAGE_BYTES);
                bulk_g2s(buf0 + (uint32_t)slot * STAGE_BYTES,
                         reg0 + (size_t)(st + DEPTH) * STAGE_F4, STAGE_BYTES,
                         mbar0 + 8u * slot);
            }
        }
        // ragged tail via direct loads (offsets stay mod 8 -> same j mapping)
        for (int idx = start + nfull * STAGE_F4 + tid; idx < end; idx += 256) {
            float4 g = __ldg(slab + idx);
            x1 += fmaxf(g.x,0.f); y1 += fmaxf(g.y,0.f);
            z1 += fmaxf(g.z,0.f); w1 += fmaxf(g.w,0.f);
        }
        const float ax = x0 + x1, ay = y0 + y1, az = z0 + z1, aw = w0 + w1;

        // start % 8 == 0 -> thread's j nibble is (tid & 7) * 4
        const int jb = (tid & 7) * 4;
        if (tid < R) sred[tid] = 0.0f;
        __syncthreads();
        atomicAdd(&sred[jb + 0], ax);
        atomicAdd(&sred[jb + 1], ay);
        atomicAdd(&sred[jb + 2], az);
        atomicAdd(&sred[jb + 3], aw);
        __syncthreads();
        if (tid < R)
            atomicAdd(&g_M[i * R + tid], sred[tid]);  // g_M zero at call entry
    }

    // ------------------- last-block-done finalize -------------------
    __syncthreads();
    if (tid == 0) {
        __threadfence();
        s_last = (atomicAdd(&g_count, 1u) == (unsigned)(NBLOCKS - 1));
    }
    __syncthreads();
    if (!s_last) return;

    // consume g_M and reset it for the next graph replay (self-cleaning)
    for (int e = tid; e < R * R; e += THREADS) {
        u.fin.sM[e] = g_M[e] + (float)V * EPS;
        g_M[e] = 0.0f;
    }
    __syncthreads();

    if (tid < R) {
        float uu = fmaxf(alpha[tid], 0.0f) + EPS;
        #pragma unroll 1
        for (int s = 0; s < NSTEP; s++) {
            float nu = 0.0f;
            #pragma unroll
            for (int k = 0; k < R; k++)
                nu = fmaf(__shfl_sync(0xffffffffu, uu, k),
                          u.fin.sM[k * R + tid], nu);
            uu = nu;                 // overflows to +inf like fp32 reference
        }
        float z = uu * (fmaxf(beta[tid], 0.0f) + EPS);
        #pragma unroll
        for (int o = 16; o; o >>= 1)
            z += __shfl_xor_sync(0xffffffffu, z, o);
        if (tid == 0) s_z = z;
    }
    __syncthreads();

    const float z = s_z;
    float lacc = 0.0f;
    for (int row = tid; row < BATCH; row += THREADS) {
        const float prob = g_pt[row] / z;
        if (out_size >= BATCH + 1)  out[1 + row] = prob;
        else if (out_size == BATCH) out[row]     = prob;
        lacc -= logf(prob + EPS);
    }
    u.fin.sloss[tid] = lacc;
    __syncthreads();
    #pragma unroll
    for (int s = THREADS / 2; s > 0; s >>= 1) {
        if (tid < s) u.fin.sloss[tid] += u.fin.sloss[tid + s];
        __syncthreads();
    }
    if (tid == 0) {
        if (out_size != BATCH) out[0] = u.fin.sloss[0] / (float)BATCH;
        g_count = 0;
    }
}

// ---------------------------------------------------------------------------
extern "C" void kernel_launch(void* const* d_in, const int* in_sizes, int n_in,
                              void* d_out, int out_size) {
    const float* alpha = (const float*)d_in[0];   // (32,)
    const float* beta  = (const float*)d_in[1];   // (32,)
    const float* core  = (const float*)d_in[2];   // (32, 50257, 32)
    const int*   ids   = (const int*)  d_in[3];   // (1024, 8)

    tjd_fused_kernel<<<NBLOCKS, THREADS>>>(alpha, beta, core, ids,
                                           (float*)d_out, out_size);
}